// round 6
// baseline (speedup 1.0000x reference)
#include <cuda_runtime.h>
#include <cuda_bf16.h>
#include <cstdint>

#define N_NODES 200000
#define N_EDGES 800000
#define D 128

// ---------------------------------------------------------------------------
// Device scratch (allocation-free rule).
// ---------------------------------------------------------------------------
__device__ float g_agg[(size_t)N_NODES * D];
__device__ __nv_bfloat16 g_W1hi[128 * 256];  // W1^T [c][k]
__device__ __nv_bfloat16 g_W1lo[128 * 256];
__device__ __nv_bfloat16 g_W2hi[128 * 128];  // W2^T [c][k]
__device__ __nv_bfloat16 g_W2lo[128 * 128];

// ---------------------------------------------------------------------------
// helpers
// ---------------------------------------------------------------------------
__device__ __forceinline__ uint32_t smem_u32(const void* p) {
    uint32_t a;
    asm("{ .reg .u64 t; cvta.to.shared.u64 t, %1; cvt.u32.u64 %0, t; }"
        : "=r"(a) : "l"(p));
    return a;
}
__device__ __forceinline__ uint32_t pack_bf16x2(float lo, float hi) {
    uint32_t r;
    asm("cvt.rn.bf16x2.f32 %0, %1, %2;" : "=r"(r) : "f"(hi), "f"(lo));
    return r;
}
__device__ __forceinline__ void split2(float v0, float v1,
                                       uint32_t& hp, uint32_t& lp) {
    hp = pack_bf16x2(v0, v1);
    float h0 = __uint_as_float(hp << 16);
    float h1 = __uint_as_float(hp & 0xffff0000u);
    lp = pack_bf16x2(v0 - h0, v1 - h1);
}
__device__ __forceinline__ void ldsm_x4(uint32_t (&r)[4], uint32_t addr) {
    asm volatile("ldmatrix.sync.aligned.m8n8.x4.shared.b16 {%0,%1,%2,%3}, [%4];"
                 : "=r"(r[0]), "=r"(r[1]), "=r"(r[2]), "=r"(r[3]) : "r"(addr));
}
__device__ __forceinline__ void ldsm_x2(uint32_t (&r)[2], uint32_t addr) {
    asm volatile("ldmatrix.sync.aligned.m8n8.x2.shared.b16 {%0,%1}, [%2];"
                 : "=r"(r[0]), "=r"(r[1]) : "r"(addr));
}
__device__ __forceinline__ void mma_bf16(float (&d)[4], const uint32_t (&a)[4],
                                         const uint32_t (&b)[2]) {
    asm volatile(
        "mma.sync.aligned.m16n8k16.row.col.f32.bf16.bf16.f32 "
        "{%0,%1,%2,%3}, {%4,%5,%6,%7}, {%8,%9}, {%0,%1,%2,%3};"
        : "+f"(d[0]), "+f"(d[1]), "+f"(d[2]), "+f"(d[3])
        : "r"(a[0]), "r"(a[1]), "r"(a[2]), "r"(a[3]), "r"(b[0]), "r"(b[1]));
}

// ---------------------------------------------------------------------------
// Kernel 0: transposed hi/lo bf16 weights.
// ---------------------------------------------------------------------------
__global__ void prep_w_kernel(const float* __restrict__ W1,
                              const float* __restrict__ W2) {
    int i = blockIdx.x * blockDim.x + threadIdx.x;
    if (i < 128 * 256) {
        int c = i >> 8, k = i & 255;
        float v = W1[k * 128 + c];
        __nv_bfloat16 h = __float2bfloat16(v);
        g_W1hi[c * 256 + k] = h;
        g_W1lo[c * 256 + k] = __float2bfloat16(v - __bfloat162float(h));
    }
    if (i < 128 * 128) {
        int c = i >> 7, k = i & 127;
        float v = W2[k * 128 + c];
        __nv_bfloat16 h = __float2bfloat16(v);
        g_W2hi[c * 128 + k] = h;
        g_W2lo[c * 128 + k] = __float2bfloat16(v - __bfloat162float(h));
    }
}

// ---------------------------------------------------------------------------
// Kernel 1: zero agg.
// ---------------------------------------------------------------------------
__global__ void zero_agg_kernel() {
    size_t i = (size_t)blockIdx.x * blockDim.x + threadIdx.x;
    if (i < (size_t)N_NODES * D / 4)
        ((float4*)g_agg)[i] = make_float4(0.f, 0.f, 0.f, 0.f);
}

// ---------------------------------------------------------------------------
// Kernel 2: scatter-add with vector reduction.
// ---------------------------------------------------------------------------
__global__ void scatter_kernel(const float* __restrict__ edge_attr,
                               const int* __restrict__ recv) {
    unsigned idx = blockIdx.x * blockDim.x + threadIdx.x;
    if (idx >= (unsigned)N_EDGES * 32u) return;
    unsigned e = idx >> 5;
    unsigned q = idx & 31u;
    int r = __ldg(recv + e);
    float4 v = ((const float4*)edge_attr)[(size_t)e * 32 + q];
    float* dst = g_agg + (size_t)r * D + (size_t)q * 4;
    asm volatile("red.global.add.v4.f32 [%0], {%1, %2, %3, %4};"
                 :: "l"(dst), "f"(v.x), "f"(v.y), "f"(v.z), "f"(v.w)
                 : "memory");
}

// ---------------------------------------------------------------------------
// Kernel 3: mma.sync bf16 3-term MLP.  M=64 nodes/CTA for 2 CTAs/SM overlap.
//   8 warps = 2(M) x 4(N); warp tile 32x32.
//   GEMM1: K=256 in 2 chunks of 128. GEMM2: K=128 (H reuses A buffers).
// SMEM tiles [rows][PITCH] bf16, PITCH=136 (272B rows, conflict-free ldmatrix).
//   A tiles 64 rows (17408 B each), W tiles 128 rows (34816 B each).
// Total: 2*17408 + 2*34816 + 1024 = 105472 B -> 2 CTAs/SM.
// ---------------------------------------------------------------------------
#define PITCH 136
#define A_TILE_B (64 * PITCH * 2)       // 17408
#define W_TILE_B (128 * PITCH * 2)      // 34816
#define OFF_A_HI 0
#define OFF_A_LO (OFF_A_HI + A_TILE_B)
#define OFF_W_HI (OFF_A_LO + A_TILE_B)
#define OFF_W_LO (OFF_W_HI + W_TILE_B)
#define OFF_B1   (OFF_W_LO + W_TILE_B)
#define OFF_B2   (OFF_B1 + 512)
#define SMEM_SZ  (OFF_B2 + 512)

__global__ __launch_bounds__(256, 2) void mma_mlp_kernel(
    const float* __restrict__ x,
    const float* __restrict__ b1,
    const float* __restrict__ b2,
    float* __restrict__ out) {

    extern __shared__ char smem[];
    const uint32_t sb = smem_u32(smem);
    const int tid = threadIdx.x;
    const int lane = tid & 31;
    const int w = tid >> 5;
    const int mw = (w & 1) * 32;          // warp M origin (0/32)
    const int nw = (w >> 1) * 32;         // warp N origin (0/32/64/96)

    const int node0 = blockIdx.x * 64;    // 200000 = 3125 * 64 exactly

    float* sB1 = (float*)(smem + OFF_B1);
    float* sB2 = (float*)(smem + OFF_B2);
    if (tid < 128) { sB1[tid] = b1[tid]; sB2[tid] = b2[tid]; }

    const int arow = lane & 15;
    const int acol = (lane >> 4) * 8;
    const int brow = lane & 7;
    const int bcol = ((lane >> 3) & 1) * 8;

    float acc[2][4][4];
    #pragma unroll
    for (int mt = 0; mt < 2; ++mt)
        #pragma unroll
        for (int nt = 0; nt < 4; ++nt)
            #pragma unroll
            for (int e = 0; e < 4; ++e) acc[mt][nt][e] = 0.f;

    // =================== GEMM1: 2 K-chunks of 128 ===================
    for (int kc = 0; kc < 2; ++kc) {
        const float* src = kc ? g_agg : x;

        // --- convert A chunk: [64 rows][128 k] fp32 -> hi/lo bf16 ---
        #pragma unroll
        for (int j = 0; j < 8; ++j) {
            int i = tid + j * 256;                 // 0..2047
            int r = i >> 5, f4 = i & 31;
            float4 v = *(const float4*)(src + (size_t)(node0 + r) * 128 + f4 * 4);
            uint32_t h0, l0, h1, l1;
            split2(v.x, v.y, h0, l0);
            split2(v.z, v.w, h1, l1);
            uint32_t off = (uint32_t)(r * PITCH + f4 * 4) * 2;
            asm volatile("st.shared.v2.u32 [%0], {%1, %2};"
                         :: "r"(sb + OFF_A_HI + off), "r"(h0), "r"(h1));
            asm volatile("st.shared.v2.u32 [%0], {%1, %2};"
                         :: "r"(sb + OFF_A_LO + off), "r"(l0), "r"(l1));
        }
        // --- copy W1 chunk: [128 n][128 k] hi/lo ---
        #pragma unroll
        for (int j = 0; j < 8; ++j) {
            int i = tid + j * 256;                 // 0..2047
            int r = i >> 4, f8 = i & 15;
            size_t g = (size_t)r * 256 + kc * 128 + f8 * 8;
            uint4 wh = *(const uint4*)(g_W1hi + g);
            uint4 wl = *(const uint4*)(g_W1lo + g);
            uint32_t off = (uint32_t)(r * PITCH + f8 * 8) * 2;
            asm volatile("st.shared.v4.u32 [%0], {%1, %2, %3, %4};"
                         :: "r"(sb + OFF_W_HI + off), "r"(wh.x), "r"(wh.y), "r"(wh.z), "r"(wh.w));
            asm volatile("st.shared.v4.u32 [%0], {%1, %2, %3, %4};"
                         :: "r"(sb + OFF_W_LO + off), "r"(wl.x), "r"(wl.y), "r"(wl.z), "r"(wl.w));
        }
        __syncthreads();

        #pragma unroll
        for (int ks = 0; ks < 8; ++ks) {
            uint32_t ahi[2][4], alo[2][4];
            #pragma unroll
            for (int mt = 0; mt < 2; ++mt) {
                uint32_t aoff = (uint32_t)((mw + mt * 16 + arow) * PITCH + ks * 16 + acol) * 2;
                ldsm_x4(ahi[mt], sb + OFF_A_HI + aoff);
                ldsm_x4(alo[mt], sb + OFF_A_LO + aoff);
            }
            #pragma unroll
            for (int nt = 0; nt < 4; ++nt) {
                uint32_t boff = (uint32_t)((nw + nt * 8 + brow) * PITCH + ks * 16 + bcol) * 2;
                uint32_t bhi[2], blo[2];
                ldsm_x2(bhi, sb + OFF_W_HI + boff);
                ldsm_x2(blo, sb + OFF_W_LO + boff);
                #pragma unroll
                for (int mt = 0; mt < 2; ++mt) {
                    mma_bf16(acc[mt][nt], ahi[mt], bhi);
                    mma_bf16(acc[mt][nt], alo[mt], bhi);
                    mma_bf16(acc[mt][nt], ahi[mt], blo);
                }
            }
        }
        __syncthreads();
    }

    // =================== Epilogue 1: H = relu(acc + b1) -> A buffers ========
    {
        const int r0 = lane >> 2;
        const int c0 = 2 * (lane & 3);
        #pragma unroll
        for (int mt = 0; mt < 2; ++mt) {
            #pragma unroll
            for (int nt = 0; nt < 4; ++nt) {
                int c = nw + nt * 8 + c0;
                float bb0 = sB1[c], bb1 = sB1[c + 1];
                int rA = mw + mt * 16 + r0;
                float h00 = fmaxf(acc[mt][nt][0] + bb0, 0.f);
                float h01 = fmaxf(acc[mt][nt][1] + bb1, 0.f);
                float h10 = fmaxf(acc[mt][nt][2] + bb0, 0.f);
                float h11 = fmaxf(acc[mt][nt][3] + bb1, 0.f);
                uint32_t hp0, lp0, hp1, lp1;
                split2(h00, h01, hp0, lp0);
                split2(h10, h11, hp1, lp1);
                uint32_t off0 = (uint32_t)(rA * PITCH + c) * 2;
                uint32_t off1 = (uint32_t)((rA + 8) * PITCH + c) * 2;
                asm volatile("st.shared.b32 [%0], %1;" :: "r"(sb + OFF_A_HI + off0), "r"(hp0));
                asm volatile("st.shared.b32 [%0], %1;" :: "r"(sb + OFF_A_LO + off0), "r"(lp0));
                asm volatile("st.shared.b32 [%0], %1;" :: "r"(sb + OFF_A_HI + off1), "r"(hp1));
                asm volatile("st.shared.b32 [%0], %1;" :: "r"(sb + OFF_A_LO + off1), "r"(lp1));
                #pragma unroll
                for (int e = 0; e < 4; ++e) acc[mt][nt][e] = 0.f;
            }
        }
    }
    // --- load W2 [128][128] hi/lo ---
    #pragma unroll
    for (int j = 0; j < 8; ++j) {
        int i = tid + j * 256;
        int r = i >> 4, f8 = i & 15;
        size_t g = (size_t)r * 128 + f8 * 8;
        uint4 wh = *(const uint4*)(g_W2hi + g);
        uint4 wl = *(const uint4*)(g_W2lo + g);
        uint32_t off = (uint32_t)(r * PITCH + f8 * 8) * 2;
        asm volatile("st.shared.v4.u32 [%0], {%1, %2, %3, %4};"
                     :: "r"(sb + OFF_W_HI + off), "r"(wh.x), "r"(wh.y), "r"(wh.z), "r"(wh.w));
        asm volatile("st.shared.v4.u32 [%0], {%1, %2, %3, %4};"
                     :: "r"(sb + OFF_W_LO + off), "r"(wl.x), "r"(wl.y), "r"(wl.z), "r"(wl.w));
    }
    __syncthreads();

    // =================== GEMM2: K=128 ===================
    #pragma unroll
    for (int ks = 0; ks < 8; ++ks) {
        uint32_t ahi[2][4], alo[2][4];
        #pragma unroll
        for (int mt = 0; mt < 2; ++mt) {
            uint32_t aoff = (uint32_t)((mw + mt * 16 + arow) * PITCH + ks * 16 + acol) * 2;
            ldsm_x4(ahi[mt], sb + OFF_A_HI + aoff);
            ldsm_x4(alo[mt], sb + OFF_A_LO + aoff);
        }
        #pragma unroll
        for (int nt = 0; nt < 4; ++nt) {
            uint32_t boff = (uint32_t)((nw + nt * 8 + brow) * PITCH + ks * 16 + bcol) * 2;
            uint32_t bhi[2], blo[2];
            ldsm_x2(bhi, sb + OFF_W_HI + boff);
            ldsm_x2(blo, sb + OFF_W_LO + boff);
            #pragma unroll
            for (int mt = 0; mt < 2; ++mt) {
                mma_bf16(acc[mt][nt], ahi[mt], bhi);
                mma_bf16(acc[mt][nt], alo[mt], bhi);
                mma_bf16(acc[mt][nt], ahi[mt], blo);
            }
        }
    }

    // =================== Epilogue 2: out = acc + b2 ===================
    {
        const int r0 = lane >> 2;
        const int c0 = 2 * (lane & 3);
        #pragma unroll
        for (int mt = 0; mt < 2; ++mt) {
            #pragma unroll
            for (int nt = 0; nt < 4; ++nt) {
                int c = nw + nt * 8 + c0;
                float bb0 = sB2[c], bb1 = sB2[c + 1];
                int r = mw + mt * 16 + r0;
                *(float2*)(out + (size_t)(node0 + r) * 128 + c) =
                    make_float2(acc[mt][nt][0] + bb0, acc[mt][nt][1] + bb1);
                *(float2*)(out + (size_t)(node0 + r + 8) * 128 + c) =
                    make_float2(acc[mt][nt][2] + bb0, acc[mt][nt][3] + bb1);
            }
        }
    }
}

// ---------------------------------------------------------------------------
extern "C" void kernel_launch(void* const* d_in, const int* in_sizes, int n_in,
                              void* d_out, int out_size) {
    const float* x          = (const float*)d_in[0];
    const float* edge_attr  = (const float*)d_in[1];
    const int*   edge_index = (const int*)d_in[2];   // int32
    const float* W1         = (const float*)d_in[3];
    const float* b1         = (const float*)d_in[4];
    const float* W2         = (const float*)d_in[5];
    const float* b2         = (const float*)d_in[6];
    float*       out        = (float*)d_out;

    const int* recv = edge_index + N_EDGES;

    cudaFuncSetAttribute(mma_mlp_kernel,
                         cudaFuncAttributeMaxDynamicSharedMemorySize, SMEM_SZ);

    prep_w_kernel<<<128, 256>>>(W1, W2);
    zero_agg_kernel<<<25000, 256>>>();
    scatter_kernel<<<100000, 256>>>(edge_attr, recv);
    mma_mlp_kernel<<<N_NODES / 64, 256, SMEM_SZ>>>(x, b1, b2, out);
}

// round 7
// speedup vs baseline: 1.0933x; 1.0933x over previous
#include <cuda_runtime.h>
#include <cuda_bf16.h>
#include <cstdint>

#define N_NODES 200000
#define N_EDGES 800000
#define D 128
#define NT 1563            // ceil(200000/128); last tile has 64 valid rows
#define GRID_MLP 148

// ---------------------------------------------------------------------------
// Device scratch (allocation-free rule).
// ---------------------------------------------------------------------------
__device__ float g_agg[(size_t)N_NODES * D];
// Fragment-major weights: uint4 = {hi_b0, hi_b1, lo_b0, lo_b1} per (nb, ks, lane)
__device__ uint4 g_W1f[16 * 16 * 32];   // [nb][ksg 0..15][lane]
__device__ uint4 g_W2f[16 * 8 * 32];    // [nb][ksg 0..7][lane]

// ---------------------------------------------------------------------------
// helpers
// ---------------------------------------------------------------------------
__device__ __forceinline__ uint32_t smem_u32(const void* p) {
    uint32_t a;
    asm("{ .reg .u64 t; cvta.to.shared.u64 t, %1; cvt.u32.u64 %0, t; }"
        : "=r"(a) : "l"(p));
    return a;
}
__device__ __forceinline__ uint32_t pack_bf16x2(float lo, float hi) {
    uint32_t r;
    asm("cvt.rn.bf16x2.f32 %0, %1, %2;" : "=r"(r) : "f"(hi), "f"(lo));
    return r;
}
__device__ __forceinline__ void split2(float v0, float v1,
                                       uint32_t& hp, uint32_t& lp) {
    hp = pack_bf16x2(v0, v1);
    float h0 = __uint_as_float(hp << 16);
    float h1 = __uint_as_float(hp & 0xffff0000u);
    lp = pack_bf16x2(v0 - h0, v1 - h1);
}
__device__ __forceinline__ void ldsm_x4(uint32_t (&r)[4], uint32_t addr) {
    asm volatile("ldmatrix.sync.aligned.m8n8.x4.shared.b16 {%0,%1,%2,%3}, [%4];"
                 : "=r"(r[0]), "=r"(r[1]), "=r"(r[2]), "=r"(r[3]) : "r"(addr));
}
__device__ __forceinline__ void mma_bf16(float (&d)[4], const uint32_t (&a)[4],
                                         uint32_t b0, uint32_t b1) {
    asm volatile(
        "mma.sync.aligned.m16n8k16.row.col.f32.bf16.bf16.f32 "
        "{%0,%1,%2,%3}, {%4,%5,%6,%7}, {%8,%9}, {%0,%1,%2,%3};"
        : "+f"(d[0]), "+f"(d[1]), "+f"(d[2]), "+f"(d[3])
        : "r"(a[0]), "r"(a[1]), "r"(a[2]), "r"(a[3]), "r"(b0), "r"(b1));
}
__device__ __forceinline__ void cp_async16(uint32_t dst, const void* src) {
    asm volatile("cp.async.ca.shared.global [%0], [%1], 16;"
                 :: "r"(dst), "l"(src) : "memory");
}
#define CP_COMMIT() asm volatile("cp.async.commit_group;" ::: "memory")
#define CP_WAIT0()  asm volatile("cp.async.wait_group 0;" ::: "memory")

// ---------------------------------------------------------------------------
// Kernel 0: fragment-major hi/lo bf16 weights.
// mma m16n8k16 B-frag: thread l: b0 = WT[n0+l/4][k0+2(l%4) .. +1],
//                                b1 = WT[n0+l/4][k0+8+2(l%4) .. +1]
// ---------------------------------------------------------------------------
__global__ void prep_w_kernel(const float* __restrict__ W1,
                              const float* __restrict__ W2) {
    int i = blockIdx.x * blockDim.x + threadIdx.x;
    if (i < 8192) {                       // W1: 16 nb x 16 ks x 32 lanes
        int lane = i & 31, ks = (i >> 5) & 15, nb = i >> 9;
        int n = nb * 8 + (lane >> 2);
        int k0 = ks * 16 + 2 * (lane & 3);
        float v00 = W1[(k0 + 0) * 128 + n], v01 = W1[(k0 + 1) * 128 + n];
        float v10 = W1[(k0 + 8) * 128 + n], v11 = W1[(k0 + 9) * 128 + n];
        uint32_t hb0, lb0, hb1, lb1;
        split2(v00, v01, hb0, lb0);
        split2(v10, v11, hb1, lb1);
        g_W1f[i] = make_uint4(hb0, hb1, lb0, lb1);
    }
    if (i < 4096) {                       // W2: 16 nb x 8 ks x 32 lanes
        int lane = i & 31, ks = (i >> 5) & 7, nb = i >> 8;
        int n = nb * 8 + (lane >> 2);
        int k0 = ks * 16 + 2 * (lane & 3);
        float v00 = W2[(k0 + 0) * 128 + n], v01 = W2[(k0 + 1) * 128 + n];
        float v10 = W2[(k0 + 8) * 128 + n], v11 = W2[(k0 + 9) * 128 + n];
        uint32_t hb0, lb0, hb1, lb1;
        split2(v00, v01, hb0, lb0);
        split2(v10, v11, hb1, lb1);
        g_W2f[i] = make_uint4(hb0, hb1, lb0, lb1);
    }
}

// ---------------------------------------------------------------------------
// Kernel 1: zero agg.
// ---------------------------------------------------------------------------
__global__ void zero_agg_kernel() {
    size_t i = (size_t)blockIdx.x * blockDim.x + threadIdx.x;
    if (i < (size_t)N_NODES * D / 4)
        ((float4*)g_agg)[i] = make_float4(0.f, 0.f, 0.f, 0.f);
}

// ---------------------------------------------------------------------------
// Kernel 2: scatter-add with vector reduction.
// ---------------------------------------------------------------------------
__global__ void scatter_kernel(const float* __restrict__ edge_attr,
                               const int* __restrict__ recv) {
    unsigned idx = blockIdx.x * blockDim.x + threadIdx.x;
    if (idx >= (unsigned)N_EDGES * 32u) return;
    unsigned e = idx >> 5;
    unsigned q = idx & 31u;
    int r = __ldg(recv + e);
    float4 v = ((const float4*)edge_attr)[(size_t)e * 32 + q];
    float* dst = g_agg + (size_t)r * D + (size_t)q * 4;
    asm volatile("red.global.add.v4.f32 [%0], {%1, %2, %3, %4};"
                 :: "l"(dst), "f"(v.x), "f"(v.y), "f"(v.z), "f"(v.w)
                 : "memory");
}

// ---------------------------------------------------------------------------
// Kernel 3: persistent pipelined bf16 3-term MLP.
//   148 CTAs x 512 threads, tiles of 128 nodes strided by 148.
//   Warps: 4(M) x 4(N), warp tile 32x32. W via LDG fragments (L2-hot).
// SMEM: A0 hi/lo + A1 hi/lo (4 x 34816) + fp32 stage (65536) + biases.
// ---------------------------------------------------------------------------
#define PITCH 136
#define AB_B  (128 * PITCH * 2)          // 34816
#define OFF_A0HI 0
#define OFF_A0LO (OFF_A0HI + AB_B)
#define OFF_A1HI (OFF_A0LO + AB_B)
#define OFF_A1LO (OFF_A1HI + AB_B)
#define OFF_STG  (OFF_A1LO + AB_B)       // 139264, fp32 128x128 = 65536
#define OFF_B1   (OFF_STG + 65536)
#define OFF_B2   (OFF_B1 + 512)
#define SMEM_SZ  (OFF_B2 + 512)          // 205824

__global__ __launch_bounds__(512, 1) void mma_mlp_kernel(
    const float* __restrict__ x,
    const float* __restrict__ b1,
    const float* __restrict__ b2,
    float* __restrict__ out) {

    extern __shared__ char smem[];
    const uint32_t sb = smem_u32(smem);
    const int tid = threadIdx.x;
    const int lane = tid & 31;
    const int w = tid >> 5;
    const int mw = (w & 3) * 32;
    const int nwb = (w >> 2) * 4;        // n-block base (8-col blocks)

    float* sB1 = (float*)(smem + OFF_B1);
    float* sB2 = (float*)(smem + OFF_B2);
    if (tid < 128) { sB1[tid] = b1[tid]; sB2[tid] = b2[tid]; }

    const int arow = lane & 15;
    const int acol = (lane >> 4) * 8;
    const int gr = tid >> 5;             // stage granule row base helpers
    const int gc = tid & 31;

    float acc[2][4][4];
    #pragma unroll
    for (int mt = 0; mt < 2; ++mt)
        #pragma unroll
        for (int nt = 0; nt < 4; ++nt)
            #pragma unroll
            for (int e = 0; e < 4; ++e) acc[mt][nt][e] = 0.f;

    // ---- stage load: 8 granules/thread, self-consistent sets ----
    auto stage_load = [&](const float* src, int node0, int V) {
        #pragma unroll
        for (int j = 0; j < 8; ++j) {
            int r = gr + j * 16;         // tid>>5 + j*16 : 0..127
            int rr = (r < V) ? r : (V - 1);
            cp_async16(sb + OFF_STG + (uint32_t)(r * 128 + gc * 4) * 4,
                       src + (size_t)(node0 + rr) * 128 + gc * 4);
        }
        CP_COMMIT();
    };
    // ---- convert own granules: stage -> bf16 hi/lo buffer ----
    auto convert_stage = [&](uint32_t dhi, uint32_t dlo) {
        #pragma unroll
        for (int j = 0; j < 8; ++j) {
            int r = gr + j * 16;
            float4 v = *(const float4*)(smem + OFF_STG + (r * 128 + gc * 4) * 4);
            uint32_t h0, l0, h1, l1;
            split2(v.x, v.y, h0, l0);
            split2(v.z, v.w, h1, l1);
            uint32_t off = (uint32_t)(r * PITCH + gc * 4) * 2;
            asm volatile("st.shared.v2.u32 [%0], {%1, %2};"
                         :: "r"(dhi + off), "r"(h0), "r"(h1));
            asm volatile("st.shared.v2.u32 [%0], {%1, %2};"
                         :: "r"(dlo + off), "r"(l0), "r"(l1));
        }
    };
    // ---- one MMA k-step ----
    auto mma_step = [&](uint32_t ahiB, uint32_t aloB, const uint4* wf,
                        int ksg, int nks) {
        uint32_t ahi[2][4], alo[2][4];
        #pragma unroll
        for (int mt = 0; mt < 2; ++mt) {
            uint32_t aoff = (uint32_t)((mw + mt * 16 + arow) * PITCH +
                                       (ksg & 7) * 16 + acol) * 2;
            ldsm_x4(ahi[mt], ahiB + aoff);
            ldsm_x4(alo[mt], aloB + aoff);
        }
        #pragma unroll
        for (int nt = 0; nt < 4; ++nt) {
            uint4 f = __ldg(&wf[((nwb + nt) * nks + ksg) * 32 + lane]);
            #pragma unroll
            for (int mt = 0; mt < 2; ++mt) {
                mma_bf16(acc[mt][nt], ahi[mt], f.x, f.y);
                mma_bf16(acc[mt][nt], alo[mt], f.x, f.y);
                mma_bf16(acc[mt][nt], ahi[mt], f.z, f.w);
            }
        }
    };

    // prologue: prefetch x of first tile
    int tile = blockIdx.x;
    if (tile < NT) stage_load(x, tile * 128, min(128, N_NODES - tile * 128));
    __syncthreads();   // biases visible

    for (; tile < NT; tile += GRID_MLP) {
        const int node0 = tile * 128;
        const int V = min(128, N_NODES - node0);
        const int tile_n = tile + GRID_MLP;
        const int node0n = (tile_n < NT) ? tile_n * 128 : 0;
        const int Vn = (tile_n < NT) ? min(128, N_NODES - node0n) : 128;

        // x stage ready (own granules) -> convert to A0
        CP_WAIT0();
        convert_stage(sb + OFF_A0HI, sb + OFF_A0LO);
        stage_load(g_agg, node0, V);            // agg -> stage (async)
        __syncthreads();                        // A0 visible

        // GEMM1 chunk 0 (x), first half
        #pragma unroll
        for (int ks = 0; ks < 4; ++ks)
            mma_step(sb + OFF_A0HI, sb + OFF_A0LO, g_W1f, ks, 16);
        // mid-loop: agg landed -> convert to A1; prefetch next tile's x
        CP_WAIT0();
        convert_stage(sb + OFF_A1HI, sb + OFF_A1LO);
        stage_load(x, node0n, Vn);
        // chunk 0 second half
        #pragma unroll
        for (int ks = 4; ks < 8; ++ks)
            mma_step(sb + OFF_A0HI, sb + OFF_A0LO, g_W1f, ks, 16);
        __syncthreads();                        // A1 visible

        // GEMM1 chunk 1 (agg)
        #pragma unroll
        for (int ks = 0; ks < 8; ++ks)
            mma_step(sb + OFF_A1HI, sb + OFF_A1LO, g_W1f, 8 + ks, 16);

        // Epilogue 1: H = relu(acc + b1) -> A0 buffers (disjoint from A1)
        {
            const int r0 = lane >> 2;
            const int c0 = 2 * (lane & 3);
            #pragma unroll
            for (int mt = 0; mt < 2; ++mt) {
                #pragma unroll
                for (int nt = 0; nt < 4; ++nt) {
                    int c = nwb * 8 + nt * 8 + c0;
                    float bb0 = sB1[c], bb1 = sB1[c + 1];
                    int rA = mw + mt * 16 + r0;
                    float h00 = fmaxf(acc[mt][nt][0] + bb0, 0.f);
                    float h01 = fmaxf(acc[mt][nt][1] + bb1, 0.f);
                    float h10 = fmaxf(acc[mt][nt][2] + bb0, 0.f);
                    float h11 = fmaxf(acc[mt][nt][3] + bb1, 0.f);
                    uint32_t hp0, lp0, hp1, lp1;
                    split2(h00, h01, hp0, lp0);
                    split2(h10, h11, hp1, lp1);
                    uint32_t o0 = (uint32_t)(rA * PITCH + c) * 2;
                    uint32_t o1 = (uint32_t)((rA + 8) * PITCH + c) * 2;
                    asm volatile("st.shared.b32 [%0], %1;" :: "r"(sb + OFF_A0HI + o0), "r"(hp0));
                    asm volatile("st.shared.b32 [%0], %1;" :: "r"(sb + OFF_A0LO + o0), "r"(lp0));
                    asm volatile("st.shared.b32 [%0], %1;" :: "r"(sb + OFF_A0HI + o1), "r"(hp1));
                    asm volatile("st.shared.b32 [%0], %1;" :: "r"(sb + OFF_A0LO + o1), "r"(lp1));
                    #pragma unroll
                    for (int e = 0; e < 4; ++e) acc[mt][nt][e] = 0.f;
                }
            }
        }
        __syncthreads();                        // H visible

        // GEMM2 (H @ W2)
        #pragma unroll
        for (int ks = 0; ks < 8; ++ks)
            mma_step(sb + OFF_A0HI, sb + OFF_A0LO, g_W2f, ks, 8);

        // Epilogue 2: out = acc + b2
        {
            const int r0 = lane >> 2;
            const int c0 = 2 * (lane & 3);
            #pragma unroll
            for (int mt = 0; mt < 2; ++mt) {
                #pragma unroll
                for (int nt = 0; nt < 4; ++nt) {
                    int c = nwb * 8 + nt * 8 + c0;
                    float bb0 = sB2[c], bb1 = sB2[c + 1];
                    int r = mw + mt * 16 + r0;
                    if (r < V)
                        *(float2*)(out + (size_t)(node0 + r) * 128 + c) =
                            make_float2(acc[mt][nt][0] + bb0, acc[mt][nt][1] + bb1);
                    if (r + 8 < V)
                        *(float2*)(out + (size_t)(node0 + r + 8) * 128 + c) =
                            make_float2(acc[mt][nt][2] + bb0, acc[mt][nt][3] + bb1);
                    #pragma unroll
                    for (int e = 0; e < 4; ++e) acc[mt][nt][e] = 0.f;
                }
            }
        }
        __syncthreads();   // all warps done reading A0(H) before next convert
    }
}

// ---------------------------------------------------------------------------
extern "C" void kernel_launch(void* const* d_in, const int* in_sizes, int n_in,
                              void* d_out, int out_size) {
    const float* x          = (const float*)d_in[0];
    const float* edge_attr  = (const float*)d_in[1];
    const int*   edge_index = (const int*)d_in[2];   // int32
    const float* W1         = (const float*)d_in[3];
    const float* b1         = (const float*)d_in[4];
    const float* W2         = (const float*)d_in[5];
    const float* b2         = (const float*)d_in[6];
    float*       out        = (float*)d_out;

    const int* recv = edge_index + N_EDGES;

    cudaFuncSetAttribute(mma_mlp_kernel,
                         cudaFuncAttributeMaxDynamicSharedMemorySize, SMEM_SZ);

    prep_w_kernel<<<32, 256>>>(W1, W2);
    zero_agg_kernel<<<25000, 256>>>();
    scatter_kernel<<<100000, 256>>>(edge_attr, recv);
    mma_mlp_kernel<<<GRID_MLP, 512, SMEM_SZ>>>(x, b1, b2, out);
}